// round 10
// baseline (speedup 1.0000x reference)
#include <cuda_runtime.h>
#include <cuda_fp16.h>
#include <cstdint>

#define P_PIX 32768            // H*W
#define HP    16384            // P/2
#define HPH   8192             // HP/2

// ---------------- scratch (static device globals) ----------------------------
__device__ __half g_H  [128u * 32768u];          //  8 MB hidden [128][P]
__device__ __half g_X  [256u * 32768u];          // 16 MB query_state [256][P]
__device__ __half g_Q  [256u * 32768u];          // 16 MB q [256][P]
__device__ __half g_QT [(size_t)2048u * 32768u]; // 134 MB qt channel-major [8*256][P]
__device__ __half g_V  [4u * 256u * 32768u];     // 64 MB V [4][256][P]
__device__ __half g_A  [256u * 32768u];          // 16 MB
__device__ __half g_W32[32u * 32768u];           //  2 MB softmax weights [4n*8h][P]
__device__ __half g_Wd2[256 * 128];
__device__ __half g_Wq [256 * 256];
__device__ __half g_Wv [256 * 256];
__device__ __half g_Wkt[8 * 256 * 32];           // Wk_g^T: [8][256 c][32 d]
__device__ __half g_Wo [256 * 256];
__device__ float  g_zeros[256];

// ---------------- PTX helpers -------------------------------------------------
__device__ __forceinline__ void ldmx4(uint32_t& r0, uint32_t& r1, uint32_t& r2, uint32_t& r3, uint32_t addr) {
    asm volatile("ldmatrix.sync.aligned.m8n8.x4.shared.b16 {%0,%1,%2,%3}, [%4];\n"
                 : "=r"(r0), "=r"(r1), "=r"(r2), "=r"(r3) : "r"(addr));
}
__device__ __forceinline__ void ldmx4t(uint32_t& r0, uint32_t& r1, uint32_t& r2, uint32_t& r3, uint32_t addr) {
    asm volatile("ldmatrix.sync.aligned.m8n8.x4.trans.shared.b16 {%0,%1,%2,%3}, [%4];\n"
                 : "=r"(r0), "=r"(r1), "=r"(r2), "=r"(r3) : "r"(addr));
}
__device__ __forceinline__ void mma16816(float* d, const uint32_t* a, uint32_t b0, uint32_t b1) {
    asm volatile("mma.sync.aligned.m16n8k16.row.col.f32.f16.f16.f32 "
                 "{%0,%1,%2,%3}, {%4,%5,%6,%7}, {%8,%9}, {%0,%1,%2,%3};\n"
                 : "+f"(d[0]), "+f"(d[1]), "+f"(d[2]), "+f"(d[3])
                 : "r"(a[0]), "r"(a[1]), "r"(a[2]), "r"(a[3]), "r"(b0), "r"(b1));
}
__device__ __forceinline__ void cp16(uint32_t dst, const void* src) {
    asm volatile("cp.async.cg.shared.global [%0], [%1], 16;\n" :: "r"(dst), "l"(src));
}
__device__ __forceinline__ void cp_commit() { asm volatile("cp.async.commit_group;\n"); }
template<int N> __device__ __forceinline__ void cp_wait() {
    asm volatile("cp.async.wait_group %0;\n" :: "n"(N));
}

// ---------------- prep ---------------------------------------------------------
__global__ __launch_bounds__(256)
void prep_all(const float* __restrict__ wd2, const float* __restrict__ wq,
              const float* __restrict__ wk, const float* __restrict__ wv,
              const float* __restrict__ wo,
              __half* __restrict__ Wd2, __half* __restrict__ Wq,
              __half* __restrict__ Wv, __half* __restrict__ Wkt,
              __half* __restrict__ Wo, float* __restrict__ zeros)
{
    int t = blockIdx.x * 256 + threadIdx.x;
    if (t < 32768)       Wd2[t] = __float2half_rn(wd2[t]);
    else if (t < 98304)  { int i = t - 32768;  Wq[i] = __float2half_rn(wq[i]); }
    else if (t < 163840) { int i = t - 98304;  Wv[i] = __float2half_rn(wv[i]); }
    else if (t < 229376) {
        int i = t - 163840;                    // Wkt[g][c][d] = wk[(g*32+d)*256 + c]
        int g = i >> 13, r = i & 8191;
        int c = r >> 5, d = r & 31;
        Wkt[i] = __float2half_rn(wk[(g * 32 + d) * 256 + c]);
    }
    else if (t < 294912) { int i = t - 229376; Wo[i] = __float2half_rn(wo[i]); }
    else if (t < 295168) { zeros[t - 294912] = 0.f; }
}

// ---------------- demand hidden ------------------------------------------------
__global__ __launch_bounds__(256)
void hid_kernel(const float* __restrict__ D, const float* __restrict__ w1,
                const float* __restrict__ b1, __half* __restrict__ Hout)
{
    int t = blockIdx.x * blockDim.x + threadIdx.x;
    int p = t & (P_PIX - 1);
    int c = t >> 15;
    float h = b1[c]
            + w1[c * 3 + 0] * D[p]
            + w1[c * 3 + 1] * D[P_PIX + p]
            + w1[c * 3 + 2] * D[2 * P_PIX + p];
    Hout[(size_t)c * P_PIX + p] = __float2half_rn(fmaxf(h, 0.f));
}

// ---------------- pipelined tensor-core GEMM (64x64 warp tiles) -----------------
constexpr int ASZ   = 128 * 40;
constexpr int BSZ16 = 32 * 136;
constexpr int BSZ32 = 32 * 132;
constexpr int NS16 = 4, NS32 = 3;
constexpr int SMEM16 = NS16 * (ASZ + BSZ16) * 2;
constexpr int SMEM32 = NS32 * ASZ * 2 + NS32 * BSZ32 * 4 + 2 * BSZ16 * 2;

template<bool B_HALF, bool ADD2, bool OUT_HALF>
__global__ __launch_bounds__(128)
void gemm_pipe(const __half* __restrict__ Wbase, const float* __restrict__ bias,
               const void* __restrict__ Bv,
               const float* __restrict__ add1, const float* __restrict__ add2,
               void* __restrict__ Cv,
               int K, int ldb, size_t bBatch, int batchN, int ldc, size_t cBatch,
               size_t aBatch)
{
    constexpr int NS = B_HALF ? NS16 : NS32;
    extern __shared__ __half smem[];
    __half* Asm   = smem;
    __half* Bsm16 = smem + NS * ASZ;
    float*  Bs32  = reinterpret_cast<float*>(smem + NS * ASZ);
    __half* Bcvt  = smem + NS * ASZ + NS * BSZ32 * 2;

    const int tid  = threadIdx.x;
    const int lane = tid & 31;
    const int warp = tid >> 5;
    const int warp_row = (warp & 1) * 64;
    const int warp_col = (warp >> 1) * 64;

    const int mtile0 = blockIdx.x * 128;
    const int ntile0 = blockIdx.y * 128;
    const int g  = ntile0 / batchN;
    const int p0 = ntile0 - g * batchN;

    const int KT = K >> 5;

    const __half* W = Wbase + (size_t)g * aBatch;
    const __half* Bg16 = (const __half*)Bv + (size_t)g * bBatch;
    const float*  Bg32 = (const float*)Bv  + (size_t)g * bBatch;

    auto load_stage = [&](int kt, int s) {
        int k0 = kt << 5;
        __half* As = Asm + s * ASZ;
        #pragma unroll
        for (int i = 0; i < 4; i++) {
            int idx = tid + i * 128;
            int r = idx >> 2, c8 = (idx & 3) << 3;
            cp16((uint32_t)__cvta_generic_to_shared(As + r * 40 + c8),
                 W + (size_t)(mtile0 + r) * K + k0 + c8);
        }
        if (B_HALF) {
            __half* Bs = Bsm16 + s * BSZ16;
            #pragma unroll
            for (int i = 0; i < 4; i++) {
                int idx = tid + i * 128;
                int r = idx >> 4, c8 = (idx & 15) << 3;
                cp16((uint32_t)__cvta_generic_to_shared(Bs + r * 136 + c8),
                     Bg16 + (size_t)(k0 + r) * ldb + p0 + c8);
            }
        } else {
            float* Bs = Bs32 + s * BSZ32;
            #pragma unroll
            for (int i = 0; i < 8; i++) {
                int idx = tid + i * 128;
                int r = idx >> 5, c4 = (idx & 31) << 2;
                cp16((uint32_t)__cvta_generic_to_shared(Bs + r * 132 + c4),
                     Bg32 + (size_t)(k0 + r) * ldb + p0 + c4);
            }
        }
    };

    float acc[4][8][4];
    #pragma unroll
    for (int i = 0; i < 4; i++)
        #pragma unroll
        for (int j = 0; j < 8; j++)
            #pragma unroll
            for (int t = 0; t < 4; t++) acc[i][j][t] = 0.f;

    #pragma unroll
    for (int s = 0; s < NS - 1; s++) {
        if (s < KT) load_stage(s, s);
        cp_commit();
    }

    for (int kt = 0; kt < KT; kt++) {
        cp_wait<NS - 2>();
        __syncthreads();

        int nk = kt + NS - 1;
        if (nk < KT) load_stage(nk, nk % NS);
        cp_commit();

        const int sc = kt % NS;
        const __half* As = Asm + sc * ASZ;
        const __half* Bs;
        if (B_HALF) {
            Bs = Bsm16 + sc * BSZ16;
        } else {
            __half* Bc = Bcvt + (kt & 1) * BSZ16;
            const float* Bsrc = Bs32 + sc * BSZ32;
            #pragma unroll
            for (int i = 0; i < 8; i++) {
                int idx = tid + i * 128;
                int r = idx >> 5, c4 = (idx & 31) << 2;
                float4 f = *reinterpret_cast<const float4*>(Bsrc + r * 132 + c4);
                __half2 h0 = __floats2half2_rn(f.x, f.y);
                __half2 h1 = __floats2half2_rn(f.z, f.w);
                *reinterpret_cast<uint2*>(Bc + r * 136 + c4) = make_uint2(
                    *reinterpret_cast<uint32_t*>(&h0), *reinterpret_cast<uint32_t*>(&h1));
            }
            __syncthreads();
            Bs = Bc;
        }

        #pragma unroll
        for (int kk = 0; kk < 32; kk += 16) {
            uint32_t a[4][4];
            #pragma unroll
            for (int mt = 0; mt < 4; mt++) {
                uint32_t addr = (uint32_t)__cvta_generic_to_shared(
                    As + (warp_row + mt * 16 + (lane & 15)) * 40 + kk + ((lane >> 4) << 3));
                ldmx4(a[mt][0], a[mt][1], a[mt][2], a[mt][3], addr);
            }
            #pragma unroll
            for (int j = 0; j < 4; j++) {
                uint32_t b0, b1, b2, b3;
                uint32_t addr = (uint32_t)__cvta_generic_to_shared(
                    Bs + (kk + (lane & 15)) * 136 + warp_col + j * 16 + ((lane >> 4) << 3));
                ldmx4t(b0, b1, b2, b3, addr);
                #pragma unroll
                for (int mt = 0; mt < 4; mt++) {
                    mma16816(acc[mt][2 * j],     a[mt], b0, b1);
                    mma16816(acc[mt][2 * j + 1], a[mt], b2, b3);
                }
            }
        }
    }

    // epilogue
    __half* Ch = (__half*)Cv + (size_t)g * cBatch;
    float*  Cf = (float*)Cv  + (size_t)g * cBatch;
    #pragma unroll
    for (int mt = 0; mt < 4; mt++) {
        int r = warp_row + mt * 16 + (lane >> 2);
        #pragma unroll
        for (int rr = 0; rr < 2; rr++) {
            int gr = mtile0 + r + rr * 8;
            float bsv = bias[gr];
            #pragma unroll
            for (int j = 0; j < 8; j++) {
                int px = p0 + warp_col + j * 8 + ((lane & 3) << 1);
                float v0 = acc[mt][j][rr * 2 + 0] + bsv;
                float v1 = acc[mt][j][rr * 2 + 1] + bsv;
                if (ADD2) {
                    size_t off = (size_t)gr * ldc + px;
                    float2 a1 = *reinterpret_cast<const float2*>(add1 + off);
                    float2 a2 = *reinterpret_cast<const float2*>(add2 + off);
                    v0 += a1.x + a2.x;
                    v1 += a1.y + a2.y;
                }
                if (OUT_HALF) {
                    *reinterpret_cast<__half2*>(Ch + (size_t)gr * ldc + px) =
                        __floats2half2_rn(v0, v1);
                } else {
                    *reinterpret_cast<float2*>(Cf + (size_t)gr * ldc + px) =
                        make_float2(v0, v1);
                }
            }
        }
    }
}

// ---------------- score kernel: w = softmax_n( qt . c / sqrt(32) ) --------------
// Coalesced: both qt and coll channel-major; warp lanes span consecutive pixels.
// Block: 256 thr, 128 px; thread = (px, role), role covers 4 heads.
__global__ __launch_bounds__(256)
void score_kernel(const __half* __restrict__ qt, const float* __restrict__ coll,
                  __half* __restrict__ w)
{
    __shared__ __align__(16) float  cs[4][8][128];
    __shared__ __align__(16) __half qs[8][8][128];
    const int t = threadIdx.x;
    const int p0 = blockIdx.x * 128;
    const int px = t & 127;
    const int role = t >> 7;           // heads role*4 .. role*4+3

    float acc[4][4];
    #pragma unroll
    for (int gg = 0; gg < 4; gg++)
        #pragma unroll
        for (int n = 0; n < 4; n++) acc[gg][n] = 0.f;

    for (int c0 = 0; c0 < 256; c0 += 8) {
        __syncthreads();
        #pragma unroll
        for (int i = 0; i < 4; i++) {          // coll: 1024 float4
            int idx = t + i * 256;
            int n = idx >> 8, cc = (idx >> 5) & 7, p4 = idx & 31;
            float4 f = *reinterpret_cast<const float4*>(
                coll + (size_t)(n * 256 + c0 + cc) * P_PIX + p0 + p4 * 4);
            *reinterpret_cast<float4*>(&cs[n][cc][p4 * 4]) = f;
        }
        #pragma unroll
        for (int i = 0; i < 4; i++) {          // qt: 1024 uint4 (8 halves)
            int idx = t + i * 256;
            int g = idx >> 7, cc = (idx >> 4) & 7, p8 = idx & 15;
            uint4 u = *reinterpret_cast<const uint4*>(
                qt + (size_t)(g * 256 + c0 + cc) * P_PIX + p0 + p8 * 8);
            *reinterpret_cast<uint4*>(&qs[g][cc][p8 * 8]) = u;
        }
        __syncthreads();
        #pragma unroll
        for (int cc = 0; cc < 8; cc++) {
            float cv[4];
            #pragma unroll
            for (int n = 0; n < 4; n++) cv[n] = cs[n][cc][px];
            #pragma unroll
            for (int gg = 0; gg < 4; gg++) {
                float qv = __half2float(qs[role * 4 + gg][cc][px]);
                #pragma unroll
                for (int n = 0; n < 4; n++)
                    acc[gg][n] = fmaf(qv, cv[n], acc[gg][n]);
            }
        }
    }

    const float SC = 0.17677669529663687f;     // 1/sqrt(32)
    #pragma unroll
    for (int gg = 0; gg < 4; gg++) {
        int g = role * 4 + gg;
        float s0 = acc[gg][0] * SC, s1 = acc[gg][1] * SC;
        float s2 = acc[gg][2] * SC, s3 = acc[gg][3] * SC;
        float mx = fmaxf(fmaxf(s0, s1), fmaxf(s2, s3));
        float w0 = __expf(s0 - mx), w1 = __expf(s1 - mx);
        float w2 = __expf(s2 - mx), w3 = __expf(s3 - mx);
        float inv = 1.f / (w0 + w1 + w2 + w3);
        w[(size_t)(0 * 8 + g) * P_PIX + p0 + px] = __float2half_rn(w0 * inv);
        w[(size_t)(1 * 8 + g) * P_PIX + p0 + px] = __float2half_rn(w1 * inv);
        w[(size_t)(2 * 8 + g) * P_PIX + p0 + px] = __float2half_rn(w2 * inv);
        w[(size_t)(3 * 8 + g) * P_PIX + p0 + px] = __float2half_rn(w3 * inv);
    }
}

// ---------------- apply kernel: A = sum_n w_n * V_n (half-range) ----------------
__global__ __launch_bounds__(256)
void apply_kernel(const __half* __restrict__ w, const __half* __restrict__ V,
                  __half* __restrict__ A, int ppOff)
{
    int t = blockIdx.x * blockDim.x + threadIdx.x;   // 8 * HPH threads
    int pp = ppOff + (t & (HPH - 1));
    int h  = t >> 13;

    float wx[4], wy[4];
    #pragma unroll
    for (int n = 0; n < 4; n++) {
        float2 wv2 = __half22float2(
            reinterpret_cast<const __half2*>(w)[(size_t)(n * 8 + h) * HP + pp]);
        wx[n] = wv2.x; wy[n] = wv2.y;
    }
    const __half2* V2 = reinterpret_cast<const __half2*>(V);
    __half2* A2 = reinterpret_cast<__half2*>(A);
    #pragma unroll 8
    for (int d = 0; d < 32; d++) {
        size_t row = (size_t)(h * 32 + d) * HP + pp;
        float ox = 0.f, oy = 0.f;
        #pragma unroll
        for (int n = 0; n < 4; n++) {
            float2 v = __half22float2(V2[(size_t)n * 256 * HP + row]);
            ox = fmaf(wx[n], v.x, ox);
            oy = fmaf(wy[n], v.y, oy);
        }
        A2[row] = __floats2half2_rn(ox, oy);
    }
}

// ---------------- launch ------------------------------------------------------
extern "C" void kernel_launch(void* const* d_in, const int* in_sizes, int n_in,
                              void* d_out, int out_size)
{
    const float* ego  = (const float*)d_in[0];
    const float* dem  = (const float*)d_in[1];
    const float* coll = (const float*)d_in[2];
    const float* w_d1 = (const float*)d_in[3];
    const float* b_d1 = (const float*)d_in[4];
    const float* w_d2 = (const float*)d_in[5];
    const float* b_d2 = (const float*)d_in[6];
    const float* wq   = (const float*)d_in[7];
    const float* bq   = (const float*)d_in[8];
    const float* wk   = (const float*)d_in[9];
    const float* bk   = (const float*)d_in[10];   // softmax-invariant: dropped
    const float* wv   = (const float*)d_in[11];
    const float* bv   = (const float*)d_in[12];
    const float* wo   = (const float*)d_in[13];
    const float* bo   = (const float*)d_in[14];
    const float* pos  = (const float*)d_in[15];
    (void)bk;

    __half *H, *X, *Qb, *QT, *Vb, *A, *Wb, *Wd2, *Wq, *Wv, *Wkt, *Wo;
    float *zeros;
    cudaGetSymbolAddress((void**)&H,   g_H);
    cudaGetSymbolAddress((void**)&X,   g_X);
    cudaGetSymbolAddress((void**)&Qb,  g_Q);
    cudaGetSymbolAddress((void**)&QT,  g_QT);
    cudaGetSymbolAddress((void**)&Vb,  g_V);
    cudaGetSymbolAddress((void**)&A,   g_A);
    cudaGetSymbolAddress((void**)&Wb,  g_W32);
    cudaGetSymbolAddress((void**)&Wd2, g_Wd2);
    cudaGetSymbolAddress((void**)&Wq,  g_Wq);
    cudaGetSymbolAddress((void**)&Wv,  g_Wv);
    cudaGetSymbolAddress((void**)&Wkt, g_Wkt);
    cudaGetSymbolAddress((void**)&Wo,  g_Wo);
    cudaGetSymbolAddress((void**)&zeros, g_zeros);

    static cudaStream_t s2 = nullptr, s3 = nullptr;
    static cudaEvent_t evP = nullptr, evV = nullptr, evA1 = nullptr, evO1 = nullptr;
    if (!s2) {
        cudaStreamCreateWithFlags(&s2, cudaStreamNonBlocking);
        cudaStreamCreateWithFlags(&s3, cudaStreamNonBlocking);
        cudaEventCreateWithFlags(&evP,  cudaEventDisableTiming);
        cudaEventCreateWithFlags(&evV,  cudaEventDisableTiming);
        cudaEventCreateWithFlags(&evA1, cudaEventDisableTiming);
        cudaEventCreateWithFlags(&evO1, cudaEventDisableTiming);

        cudaFuncSetAttribute(gemm_pipe<true, true, true>,
                             cudaFuncAttributeMaxDynamicSharedMemorySize, SMEM16);
        cudaFuncSetAttribute(gemm_pipe<true, false, true>,
                             cudaFuncAttributeMaxDynamicSharedMemorySize, SMEM16);
        cudaFuncSetAttribute(gemm_pipe<false, false, true>,
                             cudaFuncAttributeMaxDynamicSharedMemorySize, SMEM32);
        cudaFuncSetAttribute(gemm_pipe<true, false, false>,
                             cudaFuncAttributeMaxDynamicSharedMemorySize, SMEM16);
    }

    const int P = P_PIX;

    // ---- prep, then fork
    prep_all<<<1153, 256>>>(w_d2, wq, wk, wv, wo, Wd2, Wq, Wv, Wkt, Wo, zeros);
    cudaEventRecord(evP, 0);

    // ---- stream 2: V = Wv @ coll + bv  (M=256, N=4P, fused fp32->fp16 convert)
    cudaStreamWaitEvent(s2, evP, 0);
    gemm_pipe<false, false, true><<<dim3(2, (4 * P) / 128), 128, SMEM32, s2>>>(
        Wv, bv, coll, nullptr, nullptr, Vb,
        256, P, (size_t)256 * P, P, P, (size_t)256 * P, 0);
    cudaEventRecord(evV, s2);

    // ---- main: hid -> X -> Q -> qt -> scores (overlaps V's tensor time)
    hid_kernel<<<(128 * P) / 256, 256>>>(dem, w_d1, b_d1, H);
    gemm_pipe<true, true, true><<<dim3(2, P / 128), 128, SMEM16>>>(
        Wd2, b_d2, H, ego, pos, X, 128, P, 0, P, P, 0, 0);
    gemm_pipe<true, false, true><<<dim3(2, P / 128), 128, SMEM16>>>(
        Wq, bq, X, nullptr, nullptr, Qb, 256, P, 0, P, P, 0, 0);
    // qt[g][c][p] = sum_d Wkt[g][c][d] * Q[g*32+d][p]  (batched, K=32, channel-major out)
    gemm_pipe<true, false, true><<<dim3(2, (8 * P) / 128), 128, SMEM16>>>(
        Wkt, zeros, Qb, nullptr, nullptr, QT,
        32, P, (size_t)32 * P, P, P, (size_t)256 * P, 8192);
    // softmax weights (FMA/DRAM pipes; hidden under V GEMM)
    score_kernel<<<P / 128, 256>>>(QT, coll, Wb);

    // ---- join: apply half 1 (needs w + V)
    cudaStreamWaitEvent(0, evV, 0);
    apply_kernel<<<(8 * HPH) / 256, 256>>>(Wb, Vb, A, 0);
    cudaEventRecord(evA1, 0);

    // ---- O(half1) on s3 concurrently with apply(half2)
    cudaStreamWaitEvent(s3, evA1, 0);
    gemm_pipe<true, false, false><<<dim3(2, (P / 2) / 128), 128, SMEM16, s3>>>(
        Wo, bo, A, nullptr, nullptr, d_out, 256, P, 0, P, P, 0, 0);
    cudaEventRecord(evO1, s3);

    apply_kernel<<<(8 * HPH) / 256, 256>>>(Wb, Vb, A, HPH);

    // ---- O(half2)
    gemm_pipe<true, false, false><<<dim3(2, (P / 2) / 128), 128, SMEM16>>>(
        Wo, bo, A + HP, nullptr, nullptr, (float*)d_out + HP, 256, P, 0, P, P, 0, 0);

    cudaStreamWaitEvent(0, evO1, 0);
}

// round 11
// speedup vs baseline: 1.3465x; 1.3465x over previous
#include <cuda_runtime.h>
#include <cuda_fp16.h>
#include <cstdint>

#define P_PIX 32768            // H*W
#define HP    16384            // P/2
#define HPH   8192             // HP/2

// ---------------- scratch (static device globals) ----------------------------
__device__ __half g_H  [128u * 32768u];         //  8 MB hidden [128][P]
__device__ __half g_X  [256u * 32768u];         // 16 MB query_state fp16 [256][P]
__device__ __half g_Q  [256u * 32768u];         // 16 MB
__device__ __half g_KV [4u * 512u * 32768u];    // 128 MB per collab: K rows 0..255, V rows 256..511
__device__ __half g_A  [256u * 32768u];         // 16 MB
__device__ __half g_W32[32u * 32768u];          //  2 MB softmax weights [(n*8+h)][P]
__device__ __half g_Wd2[256 * 128];
__device__ __half g_Wq [256 * 256];
__device__ __half g_Wkv[512 * 256];
__device__ __half g_Wo [256 * 256];
__device__ float  g_bkv[512];

// ---------------- PTX helpers -------------------------------------------------
__device__ __forceinline__ void ldmx4(uint32_t& r0, uint32_t& r1, uint32_t& r2, uint32_t& r3, uint32_t addr) {
    asm volatile("ldmatrix.sync.aligned.m8n8.x4.shared.b16 {%0,%1,%2,%3}, [%4];\n"
                 : "=r"(r0), "=r"(r1), "=r"(r2), "=r"(r3) : "r"(addr));
}
__device__ __forceinline__ void ldmx4t(uint32_t& r0, uint32_t& r1, uint32_t& r2, uint32_t& r3, uint32_t addr) {
    asm volatile("ldmatrix.sync.aligned.m8n8.x4.trans.shared.b16 {%0,%1,%2,%3}, [%4];\n"
                 : "=r"(r0), "=r"(r1), "=r"(r2), "=r"(r3) : "r"(addr));
}
__device__ __forceinline__ void mma16816(float* d, const uint32_t* a, uint32_t b0, uint32_t b1) {
    asm volatile("mma.sync.aligned.m16n8k16.row.col.f32.f16.f16.f32 "
                 "{%0,%1,%2,%3}, {%4,%5,%6,%7}, {%8,%9}, {%0,%1,%2,%3};\n"
                 : "+f"(d[0]), "+f"(d[1]), "+f"(d[2]), "+f"(d[3])
                 : "r"(a[0]), "r"(a[1]), "r"(a[2]), "r"(a[3]), "r"(b0), "r"(b1));
}
__device__ __forceinline__ void mma16816h(uint32_t* d, const uint32_t* a, uint32_t b0, uint32_t b1) {
    asm volatile("mma.sync.aligned.m16n8k16.row.col.f16.f16.f16.f16 "
                 "{%0,%1}, {%2,%3,%4,%5}, {%6,%7}, {%0,%1};\n"
                 : "+r"(d[0]), "+r"(d[1])
                 : "r"(a[0]), "r"(a[1]), "r"(a[2]), "r"(a[3]), "r"(b0), "r"(b1));
}
__device__ __forceinline__ void cp16(uint32_t dst, const void* src) {
    asm volatile("cp.async.cg.shared.global [%0], [%1], 16;\n" :: "r"(dst), "l"(src));
}
__device__ __forceinline__ void cp_commit() { asm volatile("cp.async.commit_group;\n"); }
template<int N> __device__ __forceinline__ void cp_wait() {
    asm volatile("cp.async.wait_group %0;\n" :: "n"(N));
}

// ---------------- prep ---------------------------------------------------------
__global__ __launch_bounds__(256)
void prep_all(const float* __restrict__ wd2, const float* __restrict__ wq,
              const float* __restrict__ wk, const float* __restrict__ wv,
              const float* __restrict__ wo, const float* __restrict__ bk,
              const float* __restrict__ bv,
              __half* __restrict__ Wd2, __half* __restrict__ Wq,
              __half* __restrict__ Wkv, __half* __restrict__ Wo,
              float* __restrict__ bkv)
{
    int t = blockIdx.x * 256 + threadIdx.x;
    if (t < 32768)       Wd2[t] = __float2half_rn(wd2[t]);
    else if (t < 98304)  { int i = t - 32768;  Wq[i]  = __float2half_rn(wq[i]); }
    else if (t < 163840) { int i = t - 98304;  Wkv[i] = __float2half_rn(wk[i]); }
    else if (t < 229376) { int i = t - 163840; Wkv[65536 + i] = __float2half_rn(wv[i]); }
    else if (t < 294912) { int i = t - 229376; Wo[i]  = __float2half_rn(wo[i]); }
    else if (t < 295424) { int i = t - 294912; bkv[i] = (i < 256) ? bk[i] : bv[i - 256]; }
}

// ---------------- demand hidden ------------------------------------------------
__global__ __launch_bounds__(256)
void hid_kernel(const float* __restrict__ D, const float* __restrict__ w1,
                const float* __restrict__ b1, __half* __restrict__ Hout)
{
    int t = blockIdx.x * blockDim.x + threadIdx.x;
    int p = t & (P_PIX - 1);
    int c = t >> 15;
    float h = b1[c]
            + w1[c * 3 + 0] * D[p]
            + w1[c * 3 + 1] * D[P_PIX + p]
            + w1[c * 3 + 2] * D[2 * P_PIX + p];
    Hout[(size_t)c * P_PIX + p] = __float2half_rn(fmaxf(h, 0.f));
}

// ---------------- pipelined tensor-core GEMM (64x64 warp tiles) -----------------
constexpr int ASZ   = 128 * 40;
constexpr int BSZ16 = 32 * 136;
constexpr int BSZ32 = 32 * 132;
constexpr int NS16 = 4, NS32 = 3;
constexpr int SMEM16 = NS16 * (ASZ + BSZ16) * 2;
constexpr int SMEM32 = NS32 * ASZ * 2 + NS32 * BSZ32 * 4 + 2 * BSZ16 * 2;

template<bool B_HALF, bool ADD2, bool OUT_HALF, bool ACC16>
__global__ __launch_bounds__(128)
void gemm_pipe(const __half* __restrict__ W, const float* __restrict__ bias,
               const void* __restrict__ Bv,
               const float* __restrict__ add1, const float* __restrict__ add2,
               void* __restrict__ Cv,
               int K, int ldb, size_t bBatch, int batchN, int ldc, size_t cBatch)
{
    constexpr int NS = B_HALF ? NS16 : NS32;
    extern __shared__ __half smem[];
    __half* Asm   = smem;
    __half* Bsm16 = smem + NS * ASZ;
    float*  Bs32  = reinterpret_cast<float*>(smem + NS * ASZ);
    __half* Bcvt  = smem + NS * ASZ + NS * BSZ32 * 2;

    const int tid  = threadIdx.x;
    const int lane = tid & 31;
    const int warp = tid >> 5;
    const int warp_row = (warp & 1) * 64;
    const int warp_col = (warp >> 1) * 64;

    const int mtile0 = blockIdx.x * 128;
    const int ntile0 = blockIdx.y * 128;
    const int g  = ntile0 / batchN;
    const int p0 = ntile0 - g * batchN;

    const int KT = K >> 5;

    const __half* Bg16 = (const __half*)Bv + (size_t)g * bBatch;
    const float*  Bg32 = (const float*)Bv  + (size_t)g * bBatch;

    auto load_stage = [&](int kt, int s) {
        int k0 = kt << 5;
        __half* As = Asm + s * ASZ;
        #pragma unroll
        for (int i = 0; i < 4; i++) {
            int idx = tid + i * 128;
            int r = idx >> 2, c8 = (idx & 3) << 3;
            cp16((uint32_t)__cvta_generic_to_shared(As + r * 40 + c8),
                 W + (size_t)(mtile0 + r) * K + k0 + c8);
        }
        if (B_HALF) {
            __half* Bs = Bsm16 + s * BSZ16;
            #pragma unroll
            for (int i = 0; i < 4; i++) {
                int idx = tid + i * 128;
                int r = idx >> 4, c8 = (idx & 15) << 3;
                cp16((uint32_t)__cvta_generic_to_shared(Bs + r * 136 + c8),
                     Bg16 + (size_t)(k0 + r) * ldb + p0 + c8);
            }
        } else {
            float* Bs = Bs32 + s * BSZ32;
            #pragma unroll
            for (int i = 0; i < 8; i++) {
                int idx = tid + i * 128;
                int r = idx >> 5, c4 = (idx & 31) << 2;
                cp16((uint32_t)__cvta_generic_to_shared(Bs + r * 132 + c4),
                     Bg32 + (size_t)(k0 + r) * ldb + p0 + c4);
            }
        }
    };

    float    accf[ACC16 ? 1 : 4][8][4];
    uint32_t acch[ACC16 ? 4 : 1][8][2];
    #pragma unroll
    for (int i = 0; i < (ACC16 ? 1 : 4); i++)
        #pragma unroll
        for (int j = 0; j < 8; j++)
            #pragma unroll
            for (int t = 0; t < 4; t++) accf[i][j][t] = 0.f;
    #pragma unroll
    for (int i = 0; i < (ACC16 ? 4 : 1); i++)
        #pragma unroll
        for (int j = 0; j < 8; j++) { acch[i][j][0] = 0u; acch[i][j][1] = 0u; }

    #pragma unroll
    for (int s = 0; s < NS - 1; s++) {
        if (s < KT) load_stage(s, s);
        cp_commit();
    }

    for (int kt = 0; kt < KT; kt++) {
        cp_wait<NS - 2>();
        __syncthreads();

        int nk = kt + NS - 1;
        if (nk < KT) load_stage(nk, nk % NS);
        cp_commit();

        const int sc = kt % NS;
        const __half* As = Asm + sc * ASZ;
        const __half* Bs;
        if (B_HALF) {
            Bs = Bsm16 + sc * BSZ16;
        } else {
            __half* Bc = Bcvt + (kt & 1) * BSZ16;
            const float* Bsrc = Bs32 + sc * BSZ32;
            #pragma unroll
            for (int i = 0; i < 8; i++) {
                int idx = tid + i * 128;
                int r = idx >> 5, c4 = (idx & 31) << 2;
                float4 f = *reinterpret_cast<const float4*>(Bsrc + r * 132 + c4);
                __half2 h0 = __floats2half2_rn(f.x, f.y);
                __half2 h1 = __floats2half2_rn(f.z, f.w);
                *reinterpret_cast<uint2*>(Bc + r * 136 + c4) = make_uint2(
                    *reinterpret_cast<uint32_t*>(&h0), *reinterpret_cast<uint32_t*>(&h1));
            }
            __syncthreads();
            Bs = Bc;
        }

        #pragma unroll
        for (int kk = 0; kk < 32; kk += 16) {
            uint32_t a[4][4];
            #pragma unroll
            for (int mt = 0; mt < 4; mt++) {
                uint32_t addr = (uint32_t)__cvta_generic_to_shared(
                    As + (warp_row + mt * 16 + (lane & 15)) * 40 + kk + ((lane >> 4) << 3));
                ldmx4(a[mt][0], a[mt][1], a[mt][2], a[mt][3], addr);
            }
            #pragma unroll
            for (int j = 0; j < 4; j++) {
                uint32_t b0, b1, b2, b3;
                uint32_t addr = (uint32_t)__cvta_generic_to_shared(
                    Bs + (kk + (lane & 15)) * 136 + warp_col + j * 16 + ((lane >> 4) << 3));
                ldmx4t(b0, b1, b2, b3, addr);
                #pragma unroll
                for (int mt = 0; mt < 4; mt++) {
                    if (ACC16) {
                        mma16816h(acch[mt][2 * j],     a[mt], b0, b1);
                        mma16816h(acch[mt][2 * j + 1], a[mt], b2, b3);
                    } else {
                        mma16816(accf[mt][2 * j],     a[mt], b0, b1);
                        mma16816(accf[mt][2 * j + 1], a[mt], b2, b3);
                    }
                }
            }
        }
    }

    // epilogue
    __half* Ch = (__half*)Cv + (size_t)g * cBatch;
    float*  Cf = (float*)Cv  + (size_t)g * cBatch;
    #pragma unroll
    for (int mt = 0; mt < 4; mt++) {
        int r = warp_row + mt * 16 + (lane >> 2);
        #pragma unroll
        for (int rr = 0; rr < 2; rr++) {
            int gr = mtile0 + r + rr * 8;
            float bsv = bias[gr];
            #pragma unroll
            for (int j = 0; j < 8; j++) {
                int px = p0 + warp_col + j * 8 + ((lane & 3) << 1);
                float v0, v1;
                if (ACC16) {
                    __half2 hh = *reinterpret_cast<__half2*>(&acch[mt][j][rr]);
                    v0 = __half2float(__low2half(hh))  + bsv;
                    v1 = __half2float(__high2half(hh)) + bsv;
                } else {
                    v0 = accf[mt][j][rr * 2 + 0] + bsv;
                    v1 = accf[mt][j][rr * 2 + 1] + bsv;
                }
                if (ADD2) {
                    size_t off = (size_t)gr * ldc + px;
                    float2 a1 = *reinterpret_cast<const float2*>(add1 + off);
                    float2 a2 = *reinterpret_cast<const float2*>(add2 + off);
                    v0 += a1.x + a2.x;
                    v1 += a1.y + a2.y;
                }
                if (OUT_HALF) {
                    *reinterpret_cast<__half2*>(Ch + (size_t)gr * ldc + px) =
                        __floats2half2_rn(v0, v1);
                } else {
                    *reinterpret_cast<float2*>(Cf + (size_t)gr * ldc + px) =
                        make_float2(v0, v1);
                }
            }
        }
    }
}

// ---------------- score: w = softmax_n(q . k_n / sqrt(32))  (2 px/thread) -------
__global__ __launch_bounds__(256)
void score_kernel(const __half* __restrict__ Q, const __half* __restrict__ KV,
                  __half* __restrict__ w)
{
    int t = blockIdx.x * blockDim.x + threadIdx.x;   // 8 * HP threads
    int pp = t & (HP - 1);
    int h  = t >> 14;

    const __half2* Q2 = reinterpret_cast<const __half2*>(Q + (size_t)h * 32 * P_PIX) + pp;
    float2 q[32];
    #pragma unroll
    for (int d = 0; d < 32; d++) q[d] = __half22float2(Q2[(size_t)d * HP]);

    float2 s[4];
    #pragma unroll
    for (int n = 0; n < 4; n++) {
        const __half2* K2 = reinterpret_cast<const __half2*>(
            KV + (size_t)n * 512 * P_PIX + (size_t)h * 32 * P_PIX) + pp;
        float ax = 0.f, ay = 0.f;
        #pragma unroll
        for (int d = 0; d < 32; d++) {
            float2 k = __half22float2(K2[(size_t)d * HP]);
            ax = fmaf(q[d].x, k.x, ax);
            ay = fmaf(q[d].y, k.y, ay);
        }
        s[n] = make_float2(ax * 0.17677669529663687f, ay * 0.17677669529663687f);
    }
    float mx = fmaxf(fmaxf(s[0].x, s[1].x), fmaxf(s[2].x, s[3].x));
    float my = fmaxf(fmaxf(s[0].y, s[1].y), fmaxf(s[2].y, s[3].y));
    float wx[4], wy[4], sx = 0.f, sy = 0.f;
    #pragma unroll
    for (int n = 0; n < 4; n++) {
        wx[n] = __expf(s[n].x - mx); sx += wx[n];
        wy[n] = __expf(s[n].y - my); sy += wy[n];
    }
    float ix = 1.f / sx, iy = 1.f / sy;
    __half2* w2 = reinterpret_cast<__half2*>(w);
    #pragma unroll
    for (int n = 0; n < 4; n++)
        w2[(size_t)(n * 8 + h) * HP + pp] = __floats2half2_rn(wx[n] * ix, wy[n] * iy);
}

// ---------------- apply: A = sum_n w_n * V_n (half-range) -----------------------
__global__ __launch_bounds__(256)
void apply_kernel(const __half* __restrict__ w, const __half* __restrict__ KV,
                  __half* __restrict__ A, int ppOff)
{
    int t = blockIdx.x * blockDim.x + threadIdx.x;   // 8 * HPH threads
    int pp = ppOff + (t & (HPH - 1));
    int h  = t >> 13;

    float wx[4], wy[4];
    const __half2* w2 = reinterpret_cast<const __half2*>(w);
    #pragma unroll
    for (int n = 0; n < 4; n++) {
        float2 wv2 = __half22float2(w2[(size_t)(n * 8 + h) * HP + pp]);
        wx[n] = wv2.x; wy[n] = wv2.y;
    }
    const __half2* V2 = reinterpret_cast<const __half2*>(KV);
    __half2* A2 = reinterpret_cast<__half2*>(A);
    #pragma unroll 8
    for (int d = 0; d < 32; d++) {
        float ox = 0.f, oy = 0.f;
        #pragma unroll
        for (int n = 0; n < 4; n++) {
            float2 v = __half22float2(
                V2[((size_t)n * 512 + 256 + h * 32 + d) * HP + pp]);
            ox = fmaf(wx[n], v.x, ox);
            oy = fmaf(wy[n], v.y, oy);
        }
        A2[(size_t)(h * 32 + d) * HP + pp] = __floats2half2_rn(ox, oy);
    }
}

// ---------------- launch ------------------------------------------------------
extern "C" void kernel_launch(void* const* d_in, const int* in_sizes, int n_in,
                              void* d_out, int out_size)
{
    const float* ego  = (const float*)d_in[0];
    const float* dem  = (const float*)d_in[1];
    const float* coll = (const float*)d_in[2];
    const float* w_d1 = (const float*)d_in[3];
    const float* b_d1 = (const float*)d_in[4];
    const float* w_d2 = (const float*)d_in[5];
    const float* b_d2 = (const float*)d_in[6];
    const float* wq   = (const float*)d_in[7];
    const float* bq   = (const float*)d_in[8];
    const float* wk   = (const float*)d_in[9];
    const float* bk   = (const float*)d_in[10];
    const float* wv   = (const float*)d_in[11];
    const float* bv   = (const float*)d_in[12];
    const float* wo   = (const float*)d_in[13];
    const float* bo   = (const float*)d_in[14];
    const float* pos  = (const float*)d_in[15];

    __half *H, *X, *Qb, *KV, *A, *Wb, *Wd2, *Wq, *Wkv, *Wo;
    float *bkv;
    cudaGetSymbolAddress((void**)&H,   g_H);
    cudaGetSymbolAddress((void**)&X,   g_X);
    cudaGetSymbolAddress((void**)&Qb,  g_Q);
    cudaGetSymbolAddress((void**)&KV,  g_KV);
    cudaGetSymbolAddress((void**)&A,   g_A);
    cudaGetSymbolAddress((void**)&Wb,  g_W32);
    cudaGetSymbolAddress((void**)&Wd2, g_Wd2);
    cudaGetSymbolAddress((void**)&Wq,  g_Wq);
    cudaGetSymbolAddress((void**)&Wkv, g_Wkv);
    cudaGetSymbolAddress((void**)&Wo,  g_Wo);
    cudaGetSymbolAddress((void**)&bkv, g_bkv);

    static cudaStream_t s2 = nullptr, s3 = nullptr;
    static cudaEvent_t evP = nullptr, evK = nullptr, evV = nullptr,
                       evA1 = nullptr, evO1 = nullptr, evQ = nullptr;
    if (!s2) {
        cudaStreamCreateWithFlags(&s2, cudaStreamNonBlocking);
        cudaStreamCreateWithFlags(&s3, cudaStreamNonBlocking);
        cudaEventCreateWithFlags(&evP,  cudaEventDisableTiming);
        cudaEventCreateWithFlags(&evK,  cudaEventDisableTiming);
        cudaEventCreateWithFlags(&evV,  cudaEventDisableTiming);
        cudaEventCreateWithFlags(&evA1, cudaEventDisableTiming);
        cudaEventCreateWithFlags(&evO1, cudaEventDisableTiming);
        cudaEventCreateWithFlags(&evQ,  cudaEventDisableTiming);

        cudaFuncSetAttribute(gemm_pipe<true, true, true, false>,
                             cudaFuncAttributeMaxDynamicSharedMemorySize, SMEM16);
        cudaFuncSetAttribute(gemm_pipe<true, false, true, false>,
                             cudaFuncAttributeMaxDynamicSharedMemorySize, SMEM16);
        cudaFuncSetAttribute(gemm_pipe<false, false, true, true>,
                             cudaFuncAttributeMaxDynamicSharedMemorySize, SMEM32);
        cudaFuncSetAttribute(gemm_pipe<false, false, true, false>,
                             cudaFuncAttributeMaxDynamicSharedMemorySize, SMEM32);
        cudaFuncSetAttribute(gemm_pipe<true, false, false, false>,
                             cudaFuncAttributeMaxDynamicSharedMemorySize, SMEM16);
    }

    const int P = P_PIX;

    // ---- prep, then fork
    prep_all<<<1154, 256>>>(w_d2, wq, wk, wv, wo, bk, bv, Wd2, Wq, Wkv, Wo, bkv);
    cudaEventRecord(evP, 0);

    // ---- stream 2: K GEMM (f16-acc), then V GEMM (f32-acc)
    cudaStreamWaitEvent(s2, evP, 0);
    gemm_pipe<false, false, true, true><<<dim3(2, (4 * P) / 128), 128, SMEM32, s2>>>(
        Wkv, bkv, coll, nullptr, nullptr, KV,
        256, P, (size_t)256 * P, P, P, (size_t)512 * P);
    cudaEventRecord(evK, s2);
    gemm_pipe<false, false, true, false><<<dim3(2, (4 * P) / 128), 128, SMEM32, s2>>>(
        Wkv + 65536, bkv + 256, coll, nullptr, nullptr,
        (void*)(KV + (size_t)256 * P),
        256, P, (size_t)256 * P, P, P, (size_t)512 * P);
    cudaEventRecord(evV, s2);

    // ---- main stream: hid -> X -> Q (under K's shadow)
    hid_kernel<<<(128 * P) / 256, 256>>>(dem, w_d1, b_d1, H);
    gemm_pipe<true, true, true, false><<<dim3(2, P / 128), 128, SMEM16>>>(
        Wd2, b_d2, H, ego, pos, X, 128, P, 0, P, P, 0);
    gemm_pipe<true, false, true, false><<<dim3(2, P / 128), 128, SMEM16>>>(
        Wq, bq, X, nullptr, nullptr, Qb, 256, P, 0, P, P, 0);

    // ---- score needs Q + K only: runs concurrently with the V GEMM
    cudaStreamWaitEvent(0, evK, 0);
    score_kernel<<<(8 * HP) / 256, 256>>>(Qb, KV, Wb);

    // ---- join on V: apply half 1
    cudaStreamWaitEvent(0, evV, 0);
    apply_kernel<<<(8 * HPH) / 256, 256>>>(Wb, KV, A, 0);
    cudaEventRecord(evA1, 0);

    // ---- O(half1) on s3 concurrently with apply(half2)
    cudaStreamWaitEvent(s3, evA1, 0);
    gemm_pipe<true, false, false, false><<<dim3(2, (P / 2) / 128), 128, SMEM16, s3>>>(
        Wo, bo, A, nullptr, nullptr, d_out, 256, P, 0, P, P, 0);
    cudaEventRecord(evO1, s3);

    apply_kernel<<<(8 * HPH) / 256, 256>>>(Wb, KV, A, HPH);

    // ---- O(half2)
    gemm_pipe<true, false, false, false><<<dim3(2, (P / 2) / 128), 128, SMEM16>>>(
        Wo, bo, A + HP, nullptr, nullptr, (float*)d_out + HP, 256, P, 0, P, P, 0);

    cudaStreamWaitEvent(0, evO1, 0);
}

// round 12
// speedup vs baseline: 1.5291x; 1.1357x over previous
#include <cuda_runtime.h>
#include <cuda_fp16.h>
#include <cstdint>

#define P_PIX 32768            // H*W
#define HP    16384            // P/2
#define HPH   8192             // HP/2

// ---------------- scratch (static device globals) ----------------------------
__device__ __half g_H  [128u * 32768u];         //  8 MB hidden [128][P]
__device__ __half g_X  [256u * 32768u];         // 16 MB query_state fp16 [256][P]
__device__ __half g_Q  [256u * 32768u];         // 16 MB
__device__ __half g_KV [4u * 512u * 32768u];    // 128 MB per collab: K rows 0..255, V rows 256..511
__device__ __half g_A  [256u * 32768u];         // 16 MB
__device__ __half g_C16[4u * 256u * 32768u];    // 64 MB collaborator features fp16 [4][256][P]
__device__ __half g_Wd2[256 * 128];
__device__ __half g_Wq [256 * 256];
__device__ __half g_Wkv[512 * 256];
__device__ __half g_Wo [256 * 256];
__device__ float  g_bkv[512];

// ---------------- PTX helpers -------------------------------------------------
__device__ __forceinline__ void ldmx4(uint32_t& r0, uint32_t& r1, uint32_t& r2, uint32_t& r3, uint32_t addr) {
    asm volatile("ldmatrix.sync.aligned.m8n8.x4.shared.b16 {%0,%1,%2,%3}, [%4];\n"
                 : "=r"(r0), "=r"(r1), "=r"(r2), "=r"(r3) : "r"(addr));
}
__device__ __forceinline__ void ldmx4t(uint32_t& r0, uint32_t& r1, uint32_t& r2, uint32_t& r3, uint32_t addr) {
    asm volatile("ldmatrix.sync.aligned.m8n8.x4.trans.shared.b16 {%0,%1,%2,%3}, [%4];\n"
                 : "=r"(r0), "=r"(r1), "=r"(r2), "=r"(r3) : "r"(addr));
}
__device__ __forceinline__ void mma16816(float* d, const uint32_t* a, uint32_t b0, uint32_t b1) {
    asm volatile("mma.sync.aligned.m16n8k16.row.col.f32.f16.f16.f32 "
                 "{%0,%1,%2,%3}, {%4,%5,%6,%7}, {%8,%9}, {%0,%1,%2,%3};\n"
                 : "+f"(d[0]), "+f"(d[1]), "+f"(d[2]), "+f"(d[3])
                 : "r"(a[0]), "r"(a[1]), "r"(a[2]), "r"(a[3]), "r"(b0), "r"(b1));
}
__device__ __forceinline__ void mma16816h(uint32_t* d, const uint32_t* a, uint32_t b0, uint32_t b1) {
    asm volatile("mma.sync.aligned.m16n8k16.row.col.f16.f16.f16.f16 "
                 "{%0,%1}, {%2,%3,%4,%5}, {%6,%7}, {%0,%1};\n"
                 : "+r"(d[0]), "+r"(d[1])
                 : "r"(a[0]), "r"(a[1]), "r"(a[2]), "r"(a[3]), "r"(b0), "r"(b1));
}
__device__ __forceinline__ void cp16(uint32_t dst, const void* src) {
    asm volatile("cp.async.cg.shared.global [%0], [%1], 16;\n" :: "r"(dst), "l"(src));
}
__device__ __forceinline__ void cp_commit() { asm volatile("cp.async.commit_group;\n"); }
template<int N> __device__ __forceinline__ void cp_wait() {
    asm volatile("cp.async.wait_group %0;\n" :: "n"(N));
}

// ---------------- prep ---------------------------------------------------------
__global__ __launch_bounds__(256)
void prep_all(const float* __restrict__ wd2, const float* __restrict__ wq,
              const float* __restrict__ wk, const float* __restrict__ wv,
              const float* __restrict__ wo, const float* __restrict__ bk,
              const float* __restrict__ bv,
              __half* __restrict__ Wd2, __half* __restrict__ Wq,
              __half* __restrict__ Wkv, __half* __restrict__ Wo,
              float* __restrict__ bkv)
{
    int t = blockIdx.x * 256 + threadIdx.x;
    if (t < 32768)       Wd2[t] = __float2half_rn(wd2[t]);
    else if (t < 98304)  { int i = t - 32768;  Wq[i]  = __float2half_rn(wq[i]); }
    else if (t < 163840) { int i = t - 98304;  Wkv[i] = __float2half_rn(wk[i]); }
    else if (t < 229376) { int i = t - 163840; Wkv[65536 + i] = __float2half_rn(wv[i]); }
    else if (t < 294912) { int i = t - 229376; Wo[i]  = __float2half_rn(wo[i]); }
    else if (t < 295424) { int i = t - 294912; bkv[i] = (i < 256) ? bk[i] : bv[i - 256]; }
}

// ---------------- collaborator fp32 -> fp16 (8 elems/thread) --------------------
__global__ __launch_bounds__(256)
void conv_coll(const float* __restrict__ s, __half* __restrict__ d)
{
    int t = blockIdx.x * 256 + threadIdx.x;
    float4 a = reinterpret_cast<const float4*>(s)[2 * t];
    float4 b = reinterpret_cast<const float4*>(s)[2 * t + 1];
    __half2 h0 = __floats2half2_rn(a.x, a.y), h1 = __floats2half2_rn(a.z, a.w);
    __half2 h2 = __floats2half2_rn(b.x, b.y), h3 = __floats2half2_rn(b.z, b.w);
    reinterpret_cast<uint4*>(d)[t] = make_uint4(
        *reinterpret_cast<uint32_t*>(&h0), *reinterpret_cast<uint32_t*>(&h1),
        *reinterpret_cast<uint32_t*>(&h2), *reinterpret_cast<uint32_t*>(&h3));
}

// ---------------- demand hidden ------------------------------------------------
__global__ __launch_bounds__(256)
void hid_kernel(const float* __restrict__ D, const float* __restrict__ w1,
                const float* __restrict__ b1, __half* __restrict__ Hout)
{
    int t = blockIdx.x * blockDim.x + threadIdx.x;
    int p = t & (P_PIX - 1);
    int c = t >> 15;
    float h = b1[c]
            + w1[c * 3 + 0] * D[p]
            + w1[c * 3 + 1] * D[P_PIX + p]
            + w1[c * 3 + 2] * D[2 * P_PIX + p];
    Hout[(size_t)c * P_PIX + p] = __float2half_rn(fmaxf(h, 0.f));
}

// ---------------- pipelined tensor-core GEMM (64x64 warp tiles) -----------------
constexpr int ASZ   = 128 * 40;
constexpr int BSZ16 = 32 * 136;
constexpr int NS16  = 4;
constexpr int SMEM16 = NS16 * (ASZ + BSZ16) * 2;   // 75776 B -> 2 CTAs/SM

template<bool ADD2, bool OUT_HALF, bool ACC16>
__global__ __launch_bounds__(128)
void gemm_pipe(const __half* __restrict__ W, const float* __restrict__ bias,
               const __half* __restrict__ B,
               const float* __restrict__ add1, const float* __restrict__ add2,
               void* __restrict__ Cv,
               int K, int ldb, size_t bBatch, int batchN, int ldc, size_t cBatch)
{
    constexpr int NS = NS16;
    extern __shared__ __half smem[];
    __half* Asm = smem;
    __half* Bsm = smem + NS * ASZ;

    const int tid  = threadIdx.x;
    const int lane = tid & 31;
    const int warp = tid >> 5;
    const int warp_row = (warp & 1) * 64;
    const int warp_col = (warp >> 1) * 64;

    const int mtile0 = blockIdx.x * 128;
    const int ntile0 = blockIdx.y * 128;
    const int g  = ntile0 / batchN;
    const int p0 = ntile0 - g * batchN;

    const int KT = K >> 5;
    const __half* Bg = B + (size_t)g * bBatch;

    auto load_stage = [&](int kt, int s) {
        int k0 = kt << 5;
        __half* As = Asm + s * ASZ;
        __half* Bs = Bsm + s * BSZ16;
        #pragma unroll
        for (int i = 0; i < 4; i++) {
            int idx = tid + i * 128;
            int r = idx >> 2, c8 = (idx & 3) << 3;
            cp16((uint32_t)__cvta_generic_to_shared(As + r * 40 + c8),
                 W + (size_t)(mtile0 + r) * K + k0 + c8);
        }
        #pragma unroll
        for (int i = 0; i < 4; i++) {
            int idx = tid + i * 128;
            int r = idx >> 4, c8 = (idx & 15) << 3;
            cp16((uint32_t)__cvta_generic_to_shared(Bs + r * 136 + c8),
                 Bg + (size_t)(k0 + r) * ldb + p0 + c8);
        }
    };

    float    accf[ACC16 ? 1 : 4][8][4];
    uint32_t acch[ACC16 ? 4 : 1][8][2];
    #pragma unroll
    for (int i = 0; i < (ACC16 ? 1 : 4); i++)
        #pragma unroll
        for (int j = 0; j < 8; j++)
            #pragma unroll
            for (int t = 0; t < 4; t++) accf[i][j][t] = 0.f;
    #pragma unroll
    for (int i = 0; i < (ACC16 ? 4 : 1); i++)
        #pragma unroll
        for (int j = 0; j < 8; j++) { acch[i][j][0] = 0u; acch[i][j][1] = 0u; }

    #pragma unroll
    for (int s = 0; s < NS - 1; s++) {
        if (s < KT) load_stage(s, s);
        cp_commit();
    }

    for (int kt = 0; kt < KT; kt++) {
        cp_wait<NS - 2>();
        __syncthreads();

        int nk = kt + NS - 1;
        if (nk < KT) load_stage(nk, nk % NS);
        cp_commit();

        const int sc = kt % NS;
        const __half* As = Asm + sc * ASZ;
        const __half* Bs = Bsm + sc * BSZ16;

        #pragma unroll
        for (int kk = 0; kk < 32; kk += 16) {
            uint32_t a[4][4];
            #pragma unroll
            for (int mt = 0; mt < 4; mt++) {
                uint32_t addr = (uint32_t)__cvta_generic_to_shared(
                    As + (warp_row + mt * 16 + (lane & 15)) * 40 + kk + ((lane >> 4) << 3));
                ldmx4(a[mt][0], a[mt][1], a[mt][2], a[mt][3], addr);
            }
            #pragma unroll
            for (int j = 0; j < 4; j++) {
                uint32_t b0, b1, b2, b3;
                uint32_t addr = (uint32_t)__cvta_generic_to_shared(
                    Bs + (kk + (lane & 15)) * 136 + warp_col + j * 16 + ((lane >> 4) << 3));
                ldmx4t(b0, b1, b2, b3, addr);
                #pragma unroll
                for (int mt = 0; mt < 4; mt++) {
                    if (ACC16) {
                        mma16816h(acch[mt][2 * j],     a[mt], b0, b1);
                        mma16816h(acch[mt][2 * j + 1], a[mt], b2, b3);
                    } else {
                        mma16816(accf[mt][2 * j],     a[mt], b0, b1);
                        mma16816(accf[mt][2 * j + 1], a[mt], b2, b3);
                    }
                }
            }
        }
    }

    // epilogue
    __half* Ch = (__half*)Cv + (size_t)g * cBatch;
    float*  Cf = (float*)Cv  + (size_t)g * cBatch;
    #pragma unroll
    for (int mt = 0; mt < 4; mt++) {
        int r = warp_row + mt * 16 + (lane >> 2);
        #pragma unroll
        for (int rr = 0; rr < 2; rr++) {
            int gr = mtile0 + r + rr * 8;
            float bsv = bias[gr];
            #pragma unroll
            for (int j = 0; j < 8; j++) {
                int px = p0 + warp_col + j * 8 + ((lane & 3) << 1);
                float v0, v1;
                if (ACC16) {
                    __half2 hh = *reinterpret_cast<__half2*>(&acch[mt][j][rr]);
                    v0 = __half2float(__low2half(hh))  + bsv;
                    v1 = __half2float(__high2half(hh)) + bsv;
                } else {
                    v0 = accf[mt][j][rr * 2 + 0] + bsv;
                    v1 = accf[mt][j][rr * 2 + 1] + bsv;
                }
                if (ADD2) {
                    size_t off = (size_t)gr * ldc + px;
                    float2 a1 = *reinterpret_cast<const float2*>(add1 + off);
                    float2 a2 = *reinterpret_cast<const float2*>(add2 + off);
                    v0 += a1.x + a2.x;
                    v1 += a1.y + a2.y;
                }
                if (OUT_HALF) {
                    *reinterpret_cast<__half2*>(Ch + (size_t)gr * ldc + px) =
                        __floats2half2_rn(v0, v1);
                } else {
                    *reinterpret_cast<float2*>(Cf + (size_t)gr * ldc + px) =
                        make_float2(v0, v1);
                }
            }
        }
    }
}

// ---------------- per-pixel cross attention (half2, 2 px/thread, half-range) ---
__global__ __launch_bounds__(256)
void attn_kernel(const __half* __restrict__ Q, const __half* __restrict__ KV,
                 __half* __restrict__ A, int ppOff)
{
    int t = blockIdx.x * blockDim.x + threadIdx.x;
    int pp = ppOff + (t & (HPH - 1));
    int h  = t >> 13;

    const __half2* Q2 = reinterpret_cast<const __half2*>(Q + (size_t)h * 32 * P_PIX) + pp;
    float2 q[32];
    #pragma unroll
    for (int d = 0; d < 32; d++) q[d] = __half22float2(Q2[(size_t)d * HP]);

    float2 s[4];
    #pragma unroll
    for (int n = 0; n < 4; n++) {
        const __half2* K2 = reinterpret_cast<const __half2*>(
            KV + (size_t)n * 512 * P_PIX + (size_t)h * 32 * P_PIX) + pp;
        float ax = 0.f, ay = 0.f;
        #pragma unroll
        for (int d = 0; d < 32; d++) {
            float2 k = __half22float2(K2[(size_t)d * HP]);
            ax = fmaf(q[d].x, k.x, ax);
            ay = fmaf(q[d].y, k.y, ay);
        }
        s[n] = make_float2(ax * 0.17677669529663687f, ay * 0.17677669529663687f);
    }
    float mx = fmaxf(fmaxf(s[0].x, s[1].x), fmaxf(s[2].x, s[3].x));
    float my = fmaxf(fmaxf(s[0].y, s[1].y), fmaxf(s[2].y, s[3].y));
    float wx[4], wy[4], sx = 0.f, sy = 0.f;
    #pragma unroll
    for (int n = 0; n < 4; n++) {
        wx[n] = __expf(s[n].x - mx); sx += wx[n];
        wy[n] = __expf(s[n].y - my); sy += wy[n];
    }
    float ix = 1.f / sx, iy = 1.f / sy;
    #pragma unroll
    for (int n = 0; n < 4; n++) { wx[n] *= ix; wy[n] *= iy; }

    __half2* A2 = reinterpret_cast<__half2*>(A + (size_t)h * 32 * P_PIX) + pp;
    #pragma unroll
    for (int d = 0; d < 32; d++) {
        float ox = 0.f, oy = 0.f;
        #pragma unroll
        for (int n = 0; n < 4; n++) {
            float2 v = __half22float2(*(reinterpret_cast<const __half2*>(
                KV + (size_t)n * 512 * P_PIX + (size_t)(256 + h * 32 + d) * P_PIX) + pp));
            ox = fmaf(wx[n], v.x, ox);
            oy = fmaf(wy[n], v.y, oy);
        }
        A2[(size_t)d * HP] = __floats2half2_rn(ox, oy);
    }
}

// ---------------- launch ------------------------------------------------------
extern "C" void kernel_launch(void* const* d_in, const int* in_sizes, int n_in,
                              void* d_out, int out_size)
{
    const float* ego  = (const float*)d_in[0];
    const float* dem  = (const float*)d_in[1];
    const float* coll = (const float*)d_in[2];
    const float* w_d1 = (const float*)d_in[3];
    const float* b_d1 = (const float*)d_in[4];
    const float* w_d2 = (const float*)d_in[5];
    const float* b_d2 = (const float*)d_in[6];
    const float* wq   = (const float*)d_in[7];
    const float* bq   = (const float*)d_in[8];
    const float* wk   = (const float*)d_in[9];
    const float* bk   = (const float*)d_in[10];
    const float* wv   = (const float*)d_in[11];
    const float* bv   = (const float*)d_in[12];
    const float* wo   = (const float*)d_in[13];
    const float* bo   = (const float*)d_in[14];
    const float* pos  = (const float*)d_in[15];

    __half *H, *X, *Qb, *KV, *A, *C16, *Wd2, *Wq, *Wkv, *Wo;
    float *bkv;
    cudaGetSymbolAddress((void**)&H,   g_H);
    cudaGetSymbolAddress((void**)&X,   g_X);
    cudaGetSymbolAddress((void**)&Qb,  g_Q);
    cudaGetSymbolAddress((void**)&KV,  g_KV);
    cudaGetSymbolAddress((void**)&A,   g_A);
    cudaGetSymbolAddress((void**)&C16, g_C16);
    cudaGetSymbolAddress((void**)&Wd2, g_Wd2);
    cudaGetSymbolAddress((void**)&Wq,  g_Wq);
    cudaGetSymbolAddress((void**)&Wkv, g_Wkv);
    cudaGetSymbolAddress((void**)&Wo,  g_Wo);
    cudaGetSymbolAddress((void**)&bkv, g_bkv);

    static cudaStream_t s2 = nullptr, s3 = nullptr;
    static cudaEvent_t evP = nullptr, evKV = nullptr, evA1 = nullptr, evO1 = nullptr;
    if (!s2) {
        cudaStreamCreateWithFlags(&s2, cudaStreamNonBlocking);
        cudaStreamCreateWithFlags(&s3, cudaStreamNonBlocking);
        cudaEventCreateWithFlags(&evP,  cudaEventDisableTiming);
        cudaEventCreateWithFlags(&evKV, cudaEventDisableTiming);
        cudaEventCreateWithFlags(&evA1, cudaEventDisableTiming);
        cudaEventCreateWithFlags(&evO1, cudaEventDisableTiming);

        cudaFuncSetAttribute(gemm_pipe<true, true, false>,
                             cudaFuncAttributeMaxDynamicSharedMemorySize, SMEM16);
        cudaFuncSetAttribute(gemm_pipe<false, true, false>,
                             cudaFuncAttributeMaxDynamicSharedMemorySize, SMEM16);
        cudaFuncSetAttribute(gemm_pipe<false, true, true>,
                             cudaFuncAttributeMaxDynamicSharedMemorySize, SMEM16);
        cudaFuncSetAttribute(gemm_pipe<false, false, false>,
                             cudaFuncAttributeMaxDynamicSharedMemorySize, SMEM16);
    }

    const int P = P_PIX;

    // ---- prep, then fork
    prep_all<<<1154, 256>>>(w_d2, wq, wk, wv, wo, bk, bv, Wd2, Wq, Wkv, Wo, bkv);
    cudaEventRecord(evP, 0);

    // ---- stream 2: coll -> fp16 (DRAM; overlaps main's tensor work),
    //      then K GEMM (f16-acc) and V GEMM (f32-acc) on the fast fp16 path
    cudaStreamWaitEvent(s2, evP, 0);
    conv_coll<<<16384, 256, 0, s2>>>(coll, C16);
    gemm_pipe<false, true, true><<<dim3(2, (4 * P) / 128), 128, SMEM16, s2>>>(
        Wkv, bkv, C16, nullptr, nullptr, KV,
        256, P, (size_t)256 * P, P, P, (size_t)512 * P);
    gemm_pipe<false, true, false><<<dim3(2, (4 * P) / 128), 128, SMEM16, s2>>>(
        Wkv + 65536, bkv + 256, C16, nullptr, nullptr,
        (void*)(KV + (size_t)256 * P),
        256, P, (size_t)256 * P, P, P, (size_t)512 * P);
    cudaEventRecord(evKV, s2);

    // ---- main stream: hid -> X -> Q (tensor; overlaps conv + part of K)
    hid_kernel<<<(128 * P) / 256, 256>>>(dem, w_d1, b_d1, H);
    gemm_pipe<true, true, false><<<dim3(2, P / 128), 128, SMEM16>>>(
        Wd2, b_d2, H, ego, pos, X, 128, P, 0, P, P, 0);
    gemm_pipe<false, true, false><<<dim3(2, P / 128), 128, SMEM16>>>(
        Wq, bq, X, nullptr, nullptr, Qb, 256, P, 0, P, P, 0);

    // ---- join: attention half 1
    cudaStreamWaitEvent(0, evKV, 0);
    attn_kernel<<<(8 * HPH) / 256, 256>>>(Qb, KV, A, 0);
    cudaEventRecord(evA1, 0);

    // ---- O(half1) on s3 concurrently with attn(half2)
    cudaStreamWaitEvent(s3, evA1, 0);
    gemm_pipe<false, false, false><<<dim3(2, (P / 2) / 128), 128, SMEM16, s3>>>(
        Wo, bo, A, nullptr, nullptr, d_out, 256, P, 0, P, P, 0);
    cudaEventRecord(evO1, s3);

    attn_kernel<<<(8 * HPH) / 256, 256>>>(Qb, KV, A, HPH);

    // ---- O(half2)
    gemm_pipe<false, false, false><<<dim3(2, (P / 2) / 128), 128, SMEM16>>>(
        Wo, bo, A + HP, nullptr, nullptr, (float*)d_out + HP, 256, P, 0, P, P, 0);

    cudaStreamWaitEvent(0, evO1, 0);
}